// round 5
// baseline (speedup 1.0000x reference)
#include <cuda_runtime.h>

// Problem constants (fixed by the reference)
#define NN        10000            // nodes
#define DEG       32
#define CH        16
#define INDIM     4
#define BATCH     8
#define E_EDGES   (NN * DEG)       // 320000 = 512 * 625
#define WSTRIDE   (E_EDGES * CH)   // 5120000 floats between weight[i] planes
#define OUTPLANE  (NN * CH)        // 160000 floats per batch in output
#define NRES      625              // residue classes: n mod 625
#define FLATS     512              // (d,c) pairs per node
#define ROWPAD    36               // smem row stride (mult of 4 -> aligned float4)
#define DEPTH     4                // cp.async pipeline stages
#define WCHUNK    2048             // floats per weight stage: 4i * 16j * 32f

// Scratch (allocation-free: __device__ globals)
__device__ float g_xT[(NN + 1) * 32];   // [node][b*4+i], row NN = zeros (pad)
__device__ int   g_e32[E_EDGES];        // edges narrowed to int32

#define CP_ASYNC16(dst_u32, src) \
    asm volatile("cp.async.cg.shared.global [%0], [%1], 16;" :: "r"(dst_u32), "l"(src))
#define CP_COMMIT() asm volatile("cp.async.commit_group;")
#define CP_WAIT2()  asm volatile("cp.async.wait_group 2;")

// ---------------------------------------------------------------------------
// Prep: per-block int64/int32 detection, narrow edges, transpose/pad x.
// ---------------------------------------------------------------------------
__global__ void prep_kernel(const float* __restrict__ x,
                            const void*  __restrict__ edges) {
    __shared__ int s_is32;
    const int t = threadIdx.x;
    if (t == 0) s_is32 = 0;
    __syncthreads();
    if (t < 64) {
        // int64 data: every odd int32 word is a zero high-word (values<=10000)
        int slot = 2 * (t * 4999) + 1;
        if (((const int*)edges)[slot] != 0) atomicOr(&s_is32, 1);
    }
    __syncthreads();
    const bool is32 = (s_is32 != 0);

    const int gtid = blockIdx.x * blockDim.x + t;
    const int nth  = gridDim.x * blockDim.x;

    if (is32) {
        const int* e = (const int*)edges;
        for (int j = gtid; j < E_EDGES; j += nth) g_e32[j] = e[j];
    } else {
        const long long* e = (const long long*)edges;
        for (int j = gtid; j < E_EDGES; j += nth) g_e32[j] = (int)e[j];
    }

    for (int j = gtid; j < (NN + 1) * 32; j += nth) {
        int node = j >> 5;
        int k    = j & 31;                      // k = b*4 + i
        float v  = 0.0f;
        if (node < NN) v = x[((k >> 2) * NN + node) * INDIM + (k & 3)];
        g_xT[j] = v;
    }
}

// ---------------------------------------------------------------------------
// Main: one block per residue class r = n mod 625 (16 nodes share 512 rows).
//  - x rows staged in smem (coalesced gathers).
//  - Weights streamed through a 4-deep cp.async.cg smem ring: stage s holds
//    W[i][(r+625j)*512 + 32s + f] at sw[s&3][i*512 + j*32 + f].
//  - Warp w computes nodes nA=r+625w, nB=r+625(w+8); lane = 16*dpar + c,
//    stage s covers d = 2s + dpar.
// ---------------------------------------------------------------------------
__global__ __launch_bounds__(256, 2)
void lcg_main(const float* __restrict__ W, float* __restrict__ out) {
    __shared__ float sx[FLATS * ROWPAD];                    // 73728 B
    __shared__ __align__(16) float sw[DEPTH][WCHUNK];       // 32768 B
    const int r    = blockIdx.x;
    const int tid  = threadIdx.x;
    const int w    = tid >> 5;
    const int lane = tid & 31;

    // ---- cp.async mapping: thread covers (plane i0 & i0+2, node j0, f-group g0)
    const int g0 = tid & 7, j0 = (tid >> 3) & 15, i0 = tid >> 7;  // i0 in {0,1}
    const float* src0 = W + (size_t)i0 * WSTRIDE + (r + NRES * j0) * FLATS + 4 * g0;
    const float* src1 = src0 + 2 * (size_t)WSTRIDE;               // plane i0+2
    const unsigned soff = (unsigned)((i0 * 16 + j0) * 32 + 4 * g0) * 4u;
    const unsigned swb  = (unsigned)__cvta_generic_to_shared(&sw[0][0]);

    // prologue: stages 0..DEPTH-2 in flight before x staging
#pragma unroll
    for (int p = 0; p < DEPTH - 1; ++p) {
        unsigned d = swb + (unsigned)(p * WCHUNK * 4) + soff;
        CP_ASYNC16(d,        src0 + 32 * p);
        CP_ASYNC16(d + 4096, src1 + 32 * p);    // +1024 floats = +2 plane slots
        CP_COMMIT();
    }

    // ---- Stage A: warp w stages x-rows w*64 .. w*64+63 (coalesced gathers)
    {
        const int fbase = w * 64;
        const int ev0 = g_e32[r * FLATS + fbase + lane];
        const int ev1 = g_e32[r * FLATS + fbase + 32 + lane];
#pragma unroll 8
        for (int k = 0; k < 64; ++k) {
            int src = __shfl_sync(0xffffffffu, (k < 32) ? ev0 : ev1, k & 31);
            sx[(fbase + k) * ROWPAD + lane] = __ldg(&g_xT[src * 32 + lane]);
        }
    }
    __syncthreads();                               // x ready

    // ---- Stage B: pipelined compute
    const int nA = r + NRES * w;
    const int nB = r + NRES * (w + 8);

    float accA[BATCH], accB[BATCH];
#pragma unroll
    for (int b = 0; b < BATCH; ++b) { accA[b] = 0.0f; accB[b] = 0.0f; }

#pragma unroll
    for (int s = 0; s < 16; ++s) {
        CP_WAIT2();            // stage s complete (<=2 newer groups pending)
        __syncthreads();       // ...and visible to all threads

        const float* wsA = &sw[s & 3][w * 32 + lane];        // + i*512
        const float* wsB = wsA + 8 * 32;
        const float a0 = wsA[0],        a1 = wsA[512];
        const float a2 = wsA[1024],     a3 = wsA[1536];
        const float b0 = wsB[0],        b1 = wsB[512];
        const float b2 = wsB[1024],     b3 = wsB[1536];

        const float4* __restrict__ rp =
            reinterpret_cast<const float4*>(sx + (32 * s + lane) * ROWPAD);
#pragma unroll
        for (int b = 0; b < BATCH; ++b) {
            float4 v = rp[b];            // x[b, src(d,c), 0..3]
            accA[b] += v.x * a0 + v.y * a1 + v.z * a2 + v.w * a3;
            accB[b] += v.x * b0 + v.y * b1 + v.z * b2 + v.w * b3;
        }

        __syncthreads();       // everyone done with buf (s&3) before refill
        const int nx = s + DEPTH - 1;
        if (nx < 16) {
            unsigned d = swb + (unsigned)((nx & 3) * WCHUNK * 4) + soff;
            CP_ASYNC16(d,        src0 + 32 * nx);
            CP_ASYNC16(d + 4096, src1 + 32 * nx);
        }
        CP_COMMIT();           // always commit to keep group counting aligned
    }

    // ---- combine the two d-parities (lane <-> lane^16), then write out
#pragma unroll
    for (int b = 0; b < BATCH; ++b) {
        accA[b] += __shfl_xor_sync(0xffffffffu, accA[b], 16);
        accB[b] += __shfl_xor_sync(0xffffffffu, accB[b], 16);
    }

    const int c    = lane & 15;
    const int half = lane >> 4;          // 0 -> batches 0..3, 1 -> batches 4..7
#pragma unroll
    for (int k = 0; k < 4; ++k) {
        const int b = half * 4 + k;
        out[b * OUTPLANE + nA * CH + c] = half ? accA[k + 4] : accA[k];
        out[b * OUTPLANE + nB * CH + c] = half ? accB[k + 4] : accB[k];
    }
}

// ---------------------------------------------------------------------------
// Launch
// ---------------------------------------------------------------------------
extern "C" void kernel_launch(void* const* d_in, const int* in_sizes, int n_in,
                              void* d_out, int out_size) {
    const float* x     = (const float*)d_in[0];   // (8,10000,4) f32
    const void*  edges = d_in[1];                 // (320000,) int64 or int32
    const float* W     = (const float*)d_in[2];   // (4,320000,16) f32
    float*       out   = (float*)d_out;           // (8,10000,16) f32
    (void)in_sizes; (void)n_in; (void)out_size;

    prep_kernel<<<320, 256>>>(x, edges);
    lcg_main<<<NRES, 256>>>(W, out);
}

// round 6
// speedup vs baseline: 1.0310x; 1.0310x over previous
#include <cuda_runtime.h>

// Problem constants (fixed by the reference)
#define NN        10000
#define DEG       32
#define CH        16
#define INDIM     4
#define BATCH     8
#define E_EDGES   (NN * DEG)       // 320000 = 512 * 625
#define WSTRIDE   (E_EDGES * CH)   // 5120000 floats between weight[i] planes
#define OUTPLANE  (NN * CH)
#define NRES      625              // residue classes: n mod 625
#define FLATS     512              // (d,c) pairs per node
#define DEPTH     4
#define WCHUNK    2048             // floats per stage: 4i * 16j * 32f

// Scratch (allocation-free: __device__ globals)
__device__ float g_xT[(NN + 1) * 32];   // [node][b*4+i], row NN = zeros
__device__ int   g_e32[E_EDGES];

#define CP_ASYNC16(dst_u32, src) \
    asm volatile("cp.async.cg.shared.global [%0], [%1], 16;" :: "r"(dst_u32), "l"(src))
#define CP_COMMIT() asm volatile("cp.async.commit_group;")
#define CP_WAIT2()  asm volatile("cp.async.wait_group 2;")

// ---------------------------------------------------------------------------
// Prep: per-block int64/int32 detection, narrow edges, transpose/pad x.
// ---------------------------------------------------------------------------
__global__ void prep_kernel(const float* __restrict__ x,
                            const void*  __restrict__ edges) {
    __shared__ int s_is32;
    const int t = threadIdx.x;
    if (t == 0) s_is32 = 0;
    __syncthreads();
    if (t < 64) {
        int slot = 2 * (t * 4999) + 1;   // odd int32 word: 0 iff int64 layout
        if (((const int*)edges)[slot] != 0) atomicOr(&s_is32, 1);
    }
    __syncthreads();
    const bool is32 = (s_is32 != 0);

    const int gtid = blockIdx.x * blockDim.x + t;
    const int nth  = gridDim.x * blockDim.x;

    if (is32) {
        const int* e = (const int*)edges;
        for (int j = gtid; j < E_EDGES; j += nth) g_e32[j] = e[j];
    } else {
        const long long* e = (const long long*)edges;
        for (int j = gtid; j < E_EDGES; j += nth) g_e32[j] = (int)e[j];
    }

    for (int j = gtid; j < (NN + 1) * 32; j += nth) {
        int node = j >> 5;
        int k    = j & 31;                 // k = b*4 + i
        float v  = 0.0f;
        if (node < NN) v = x[((k >> 2) * NN + node) * INDIM + (k & 3)];
        g_xT[j] = v;
    }
}

// ---------------------------------------------------------------------------
// Main: block = one residue class r (16 nodes share 512 gather rows).
// 128 threads / 4 warps; warp w computes 4 nodes: n = r + 625*(w + 4k).
// x rows in swizzled smem; weights streamed via 4-deep cp.async ring.
// lane = 16*dpar + c; stage s covers d = 2s + dpar.
// ---------------------------------------------------------------------------
__global__ __launch_bounds__(128, 2)
void lcg_main(const float* __restrict__ W, float* __restrict__ out) {
    __shared__ float sx[FLATS * 32];                   // 65536 B, swizzled
    __shared__ __align__(16) float sw[DEPTH][WCHUNK];  // 32768 B
    const int r    = blockIdx.x;
    const int tid  = threadIdx.x;
    const int w    = tid >> 5;
    const int lane = tid & 31;

    // ---- cp.async mapping: thread (j0 = tid>>3, g0 = tid&7) copies, for each
    //      plane i, 16B at W[i][(r+625*j0)*512 + 32*stage + 4*g0]
    const int g0 = tid & 7, j0 = tid >> 3;
    const float* wsrc = W + (r + NRES * j0) * FLATS + 4 * g0;
    const unsigned swb = (unsigned)__cvta_generic_to_shared(&sw[0][0])
                       + (unsigned)(j0 * 32 + 4 * g0) * 4u;

#pragma unroll
    for (int p = 0; p < DEPTH - 1; ++p) {        // prologue: stages 0..2
#pragma unroll
        for (int i = 0; i < 4; ++i)
            CP_ASYNC16(swb + (unsigned)((p * WCHUNK + i * 512) * 4),
                       wsrc + (size_t)i * WSTRIDE + 32 * p);
        CP_COMMIT();
    }

    // ---- Stage A: warp w stages rows w*128 .. w*128+127 (coalesced gathers)
    {
        const int fbase = w * 128;
        int ev[4];
#pragma unroll
        for (int q = 0; q < 4; ++q)
            ev[q] = g_e32[r * FLATS + fbase + 32 * q + lane];
#pragma unroll 16
        for (int k = 0; k < 128; ++k) {
            int src = __shfl_sync(0xffffffffu, ev[k >> 5], k & 31);
            int row = fbase + k;
            sx[row * 32 + (lane ^ ((row & 7) << 2))] =
                __ldg(&g_xT[src * 32 + lane]);
        }
    }
    __syncthreads();                              // x ready

    // ---- Stage B
    float acc[4][BATCH];
#pragma unroll
    for (int k = 0; k < 4; ++k)
#pragma unroll
        for (int b = 0; b < BATCH; ++b) acc[k][b] = 0.0f;

    const int swz = lane & 7;

#pragma unroll
    for (int s = 0; s < 16; ++s) {
        CP_WAIT2();           // stage s landed (<=2 newer groups pending)
        __syncthreads();      // visible to all; also: all finished stage s-1

        // weights: node j = w + 4k, plane i -> sw[slot][i*512 + j*32 + lane]
        const float* wp = &sw[s & 3][w * 32 + lane];
        float wv[4][4];
#pragma unroll
        for (int k = 0; k < 4; ++k)
#pragma unroll
            for (int i = 0; i < 4; ++i)
                wv[k][i] = wp[128 * k + 512 * i];

        const float4* __restrict__ rp =
            reinterpret_cast<const float4*>(sx + (32 * s + lane) * 32);
#pragma unroll
        for (int b = 0; b < BATCH; ++b) {
            float4 v = rp[b ^ swz];               // logical batch b (swizzled)
#pragma unroll
            for (int k = 0; k < 4; ++k)
                acc[k][b] += v.x * wv[k][0] + v.y * wv[k][1]
                           + v.z * wv[k][2] + v.w * wv[k][3];
        }

        const int nx = s + DEPTH - 1;             // refill slot (s-1)&3: safe,
        if (nx < 16) {                            // readers done (see barrier)
#pragma unroll
            for (int i = 0; i < 4; ++i)
                CP_ASYNC16(swb + (unsigned)(((nx & 3) * WCHUNK + i * 512) * 4),
                           wsrc + (size_t)i * WSTRIDE + 32 * nx);
        }
        CP_COMMIT();                              // keep group count aligned
    }

    // ---- combine d-parities, write out
#pragma unroll
    for (int k = 0; k < 4; ++k)
#pragma unroll
        for (int b = 0; b < BATCH; ++b)
            acc[k][b] += __shfl_xor_sync(0xffffffffu, acc[k][b], 16);

    const int c    = lane & 15;
    const int half = lane >> 4;
#pragma unroll
    for (int k = 0; k < 4; ++k) {
        const int n = r + NRES * (w + 4 * k);
#pragma unroll
        for (int m = 0; m < 4; ++m) {
            const int b = half * 4 + m;
            out[b * OUTPLANE + n * CH + c] = acc[k][b];
        }
    }
}

// ---------------------------------------------------------------------------
// Launch
// ---------------------------------------------------------------------------
extern "C" void kernel_launch(void* const* d_in, const int* in_sizes, int n_in,
                              void* d_out, int out_size) {
    const float* x     = (const float*)d_in[0];   // (8,10000,4) f32
    const void*  edges = d_in[1];                 // (320000,) int64/int32
    const float* W     = (const float*)d_in[2];   // (4,320000,16) f32
    float*       out   = (float*)d_out;           // (8,10000,16) f32
    (void)in_sizes; (void)n_in; (void)out_size;

    prep_kernel<<<640, 256>>>(x, edges);
    lcg_main<<<NRES, 128>>>(W, out);
}

// round 7
// speedup vs baseline: 1.0648x; 1.0328x over previous
#include <cuda_runtime.h>

// Problem constants (fixed by the reference)
#define NN        10000
#define DEG       32
#define CH        16
#define INDIM     4
#define BATCH     8
#define E_EDGES   (NN * DEG)       // 320000 = 512 * 625
#define WSTRIDE   (E_EDGES * CH)   // 5120000 floats between weight[i] planes
#define OUTPLANE  (NN * CH)
#define NRES      625              // residue classes: n mod 625
#define FLATS     512              // (d,c) pairs per node
#define DEPTH     4                // per-warp ring slots
#define SLOTF     256              // floats per slot: 2 nodes * 4 planes * 32

// Scratch (allocation-free: __device__ globals)
__device__ float g_xT[(NN + 1) * 32];   // [node][b*4+i], row NN = zeros
__device__ int   g_e32[E_EDGES];

#define CP_ASYNC16(dst_u32, src) \
    asm volatile("cp.async.cg.shared.global [%0], [%1], 16;" :: "r"(dst_u32), "l"(src))
#define CP_COMMIT() asm volatile("cp.async.commit_group;")
#define CP_WAIT2()  asm volatile("cp.async.wait_group 2;")

// ---------------------------------------------------------------------------
// Prep: per-block int64/int32 detection, narrow edges, transpose/pad x.
// ---------------------------------------------------------------------------
__global__ void prep_kernel(const float* __restrict__ x,
                            const void*  __restrict__ edges) {
    __shared__ int s_is32;
    const int t = threadIdx.x;
    if (t == 0) s_is32 = 0;
    __syncthreads();
    if (t < 64) {
        int slot = 2 * (t * 4999) + 1;   // odd int32 word: 0 iff int64 layout
        if (((const int*)edges)[slot] != 0) atomicOr(&s_is32, 1);
    }
    __syncthreads();
    const bool is32 = (s_is32 != 0);

    const int gtid = blockIdx.x * blockDim.x + t;
    const int nth  = gridDim.x * blockDim.x;

    if (is32) {
        const int* e = (const int*)edges;
        for (int j = gtid; j < E_EDGES; j += nth) g_e32[j] = e[j];
    } else {
        const long long* e = (const long long*)edges;
        for (int j = gtid; j < E_EDGES; j += nth) g_e32[j] = (int)e[j];
    }

    for (int j = gtid; j < (NN + 1) * 32; j += nth) {
        int node = j >> 5;
        int k    = j & 31;                 // k = b*4 + i
        float v  = 0.0f;
        if (node < NN) v = x[((k >> 2) * NN + node) * INDIM + (k & 3)];
        g_xT[j] = v;
    }
}

// ---------------------------------------------------------------------------
// Main: block = one residue class r (16 nodes share the 512 gather rows).
// 256 threads / 8 warps; warp w computes nA = r+625w, nB = r+625(w+8).
// x rows staged once in swizzled smem (one __syncthreads total).
// Weights: PER-WARP 4-deep cp.async ring -> no block barriers in main loop.
// lane = 16*dpar + c; stage s covers d = 2s + dpar; flat = 32s + lane.
// ---------------------------------------------------------------------------
__global__ __launch_bounds__(256, 2)
void lcg_main(const float* __restrict__ W, float* __restrict__ out) {
    __shared__ float sx[FLATS * 32];                         // 65536 B
    __shared__ __align__(16) float sw[8][DEPTH][SLOTF];      // 32768 B
    const int r    = blockIdx.x;
    const int tid  = threadIdx.x;
    const int w    = tid >> 5;
    const int lane = tid & 31;

    const int nA = r + NRES * w;
    const int nB = r + NRES * (w + 8);

    // ---- per-lane cp.async tasks k0 = lane, k1 = lane+32 of 64:
    //      k -> (jj = k>>5, i = (k>>3)&3, g = k&7); 16B each
    const int i0 = (lane >> 3) & 3, gg = lane & 7;
    const float* src0 = W + (size_t)i0 * WSTRIDE + (size_t)nA * FLATS + 4 * gg;
    const float* src1 = W + (size_t)i0 * WSTRIDE + (size_t)nB * FLATS + 4 * gg;
    const unsigned swb = (unsigned)__cvta_generic_to_shared(&sw[w][0][0]);
    const unsigned d0  = (unsigned)((i0 * 32 + 4 * gg) * 4);         // jj=0
    const unsigned d1  = d0 + 128 * 4;                               // jj=1

    // prologue: stages 0..2 in flight (overlaps the x staging below)
#pragma unroll
    for (int p = 0; p < DEPTH - 1; ++p) {
        const unsigned sb = (unsigned)(p * SLOTF * 4);
        CP_ASYNC16(swb + sb + d0, src0 + 32 * p);
        CP_ASYNC16(swb + sb + d1, src1 + 32 * p);
        CP_COMMIT();
    }

    // ---- Stage A: warp w stages rows w*64 .. w*64+63 (coalesced gathers)
    {
        const int fbase = w * 64;
        const int ev0 = g_e32[r * FLATS + fbase + lane];
        const int ev1 = g_e32[r * FLATS + fbase + 32 + lane];
#pragma unroll 8
        for (int k = 0; k < 64; ++k) {
            int src = __shfl_sync(0xffffffffu, (k < 32) ? ev0 : ev1, k & 31);
            int row = fbase + k;
            sx[row * 32 + (lane ^ ((row & 7) << 2))] =
                __ldg(&g_xT[src * 32 + lane]);
        }
    }
    __syncthreads();                       // the only block barrier

    // ---- Stage B: per-warp pipelined compute (no block syncs)
    float accA[BATCH], accB[BATCH];
#pragma unroll
    for (int b = 0; b < BATCH; ++b) { accA[b] = 0.0f; accB[b] = 0.0f; }

    const int swz = lane & 7;

#pragma unroll
    for (int s = 0; s < 16; ++s) {
        CP_WAIT2();                        // own groups: stage s landed
        __syncwarp();                      // all lanes' copies visible

        const float* wp = &sw[w][s & 3][lane];
        const float a0 = wp[0],   a1 = wp[32],  a2 = wp[64],  a3 = wp[96];
        const float b0 = wp[128], b1 = wp[160], b2 = wp[192], b3 = wp[224];

        const float4* __restrict__ rp =
            reinterpret_cast<const float4*>(sx + (32 * s + lane) * 32);
#pragma unroll
        for (int b = 0; b < BATCH; ++b) {
            float4 v = rp[b ^ swz];        // logical batch b (swizzled)
            accA[b] += v.x * a0 + v.y * a1 + v.z * a2 + v.w * a3;
            accB[b] += v.x * b0 + v.y * b1 + v.z * b2 + v.w * b3;
        }

        const int nx = s + DEPTH - 1;      // refill slot (s-1)&3: this warp's
        if (nx < 16) {                     // lanes all finished reading it
            const unsigned sb = (unsigned)((nx & 3) * SLOTF * 4);
            CP_ASYNC16(swb + sb + d0, src0 + 32 * nx);
            CP_ASYNC16(swb + sb + d1, src1 + 32 * nx);
        }
        CP_COMMIT();                       // keep group counting aligned
    }

    // ---- combine d-parities (lane <-> lane^16), write out
#pragma unroll
    for (int b = 0; b < BATCH; ++b) {
        accA[b] += __shfl_xor_sync(0xffffffffu, accA[b], 16);
        accB[b] += __shfl_xor_sync(0xffffffffu, accB[b], 16);
    }

    const int c    = lane & 15;
    const int half = lane >> 4;            // 0 -> batches 0..3, 1 -> 4..7
#pragma unroll
    for (int k = 0; k < 4; ++k) {
        const int b = half * 4 + k;
        out[b * OUTPLANE + nA * CH + c] = half ? accA[k + 4] : accA[k];
        out[b * OUTPLANE + nB * CH + c] = half ? accB[k + 4] : accB[k];
    }
}

// ---------------------------------------------------------------------------
// Launch
// ---------------------------------------------------------------------------
extern "C" void kernel_launch(void* const* d_in, const int* in_sizes, int n_in,
                              void* d_out, int out_size) {
    const float* x     = (const float*)d_in[0];   // (8,10000,4) f32
    const void*  edges = d_in[1];                 // (320000,) int64/int32
    const float* W     = (const float*)d_in[2];   // (4,320000,16) f32
    float*       out   = (float*)d_out;           // (8,10000,16) f32
    (void)in_sizes; (void)n_in; (void)out_size;

    prep_kernel<<<640, 256>>>(x, edges);
    lcg_main<<<NRES, 256>>>(W, out);
}

// round 8
// speedup vs baseline: 1.1159x; 1.0480x over previous
#include <cuda_runtime.h>

// Problem constants (fixed by the reference)
#define NN        10000
#define DEG       32
#define CH        16
#define INDIM     4
#define BATCH     8
#define E_EDGES   (NN * DEG)       // 320000 = 512 * 625
#define WSTRIDE   (E_EDGES * CH)   // 5120000 floats between weight[i] planes
#define OUTPLANE  (NN * CH)
#define NRES      625              // residue classes: n mod 625
#define FLATS     512              // (d,c) pairs per node
#define DEPTH     4
#define XSLOTF    1024             // x slot: 32 rows * 32 floats (4 KB)
#define WSLOTF    512              // w slot per warp: 4n*4i*32 (2 KB)

// Scratch (allocation-free: __device__ globals)
__device__ float g_xT[(NN + 1) * 32];   // [node][b*4+i], row NN = zeros
__device__ int   g_e32[E_EDGES];

#define CP_ASYNC16(dst_u32, src) \
    asm volatile("cp.async.cg.shared.global [%0], [%1], 16;" :: "r"(dst_u32), "l"(src))
#define CP_COMMIT() asm volatile("cp.async.commit_group;")
#define CP_WAIT2()  asm volatile("cp.async.wait_group 2;")

// ---------------------------------------------------------------------------
// Prep: per-block int64/int32 detection, narrow edges, transpose/pad x.
// ---------------------------------------------------------------------------
__global__ void prep_kernel(const float* __restrict__ x,
                            const void*  __restrict__ edges) {
    __shared__ int s_is32;
    const int t = threadIdx.x;
    if (t == 0) s_is32 = 0;
    __syncthreads();
    if (t < 64) {
        int slot = 2 * (t * 4999) + 1;   // odd int32 word: 0 iff int64 layout
        if (((const int*)edges)[slot] != 0) atomicOr(&s_is32, 1);
    }
    __syncthreads();
    const bool is32 = (s_is32 != 0);

    const int gtid = blockIdx.x * blockDim.x + t;
    const int nth  = gridDim.x * blockDim.x;

    if (is32) {
        const int* e = (const int*)edges;
        for (int j = gtid; j < E_EDGES; j += nth) g_e32[j] = e[j];
    } else {
        const long long* e = (const long long*)edges;
        for (int j = gtid; j < E_EDGES; j += nth) g_e32[j] = (int)e[j];
    }

    for (int j = gtid; j < (NN + 1) * 32; j += nth) {
        int node = j >> 5;
        int k    = j & 31;                 // k = b*4 + i
        float v  = 0.0f;
        if (node < NN) v = x[((k >> 2) * NN + node) * INDIM + (k & 3)];
        g_xT[j] = v;
    }
}

// ---------------------------------------------------------------------------
// Main: block (128 thr, 4 warps) = one residue class r; warp w computes the
// 4 nodes n = r + 625*(w + 4k), k=0..3.
// Stage s covers flats 32s..32s+31 (d = 2s + dpar, lane = 16*dpar + c).
//  - x window: block-shared 4-deep cp.async ring of 32 gathered rows/stage,
//    XOR-swizzled; each x-row read feeds 4 nodes (halves x LDS traffic).
//  - weights: per-warp private 4-deep cp.async ring (own wait_group only).
// One __syncthreads per stage (x window is block-shared).
// ---------------------------------------------------------------------------
__global__ __launch_bounds__(128, 4)
void lcg_main(const float* __restrict__ W, float* __restrict__ out) {
    __shared__ __align__(16) float xr[DEPTH][XSLOTF];      // 16384 B
    __shared__ __align__(16) float wr[4][DEPTH][WSLOTF];   // 32768 B
    const int r    = blockIdx.x;
    const int w    = threadIdx.x >> 5;
    const int lane = threadIdx.x & 31;

    // ---- per-lane cp.async geometry
    const int ii = lane >> 3;              // weight plane i (0..3)
    const int gg = lane & 7;               // 16B chunk within 32-float row

    // weight sources: task q -> node n_q = r + 625*(w + 4q), plane ii, chunk gg
    const float* wsrc[4];
#pragma unroll
    for (int q = 0; q < 4; ++q)
        wsrc[q] = W + (size_t)ii * WSTRIDE
                    + (size_t)(r + NRES * (w + 4 * q)) * FLATS + 4 * gg;
    const unsigned wrb = (unsigned)__cvta_generic_to_shared(&wr[w][0][0]);
    // dst offset for task q: ((q*4 + ii)*32 + 4*gg) floats
    unsigned wdst[4];
#pragma unroll
    for (int q = 0; q < 4; ++q)
        wdst[q] = (unsigned)(((q * 4 + ii) * 32 + 4 * gg) * 4);

    // x gather: tasks t = lane, lane+32 -> local row jj = 8w + (t>>3)... but
    // block rows 0..31 split: warp w fills rows 8w..8w+7; lane covers
    // j0 = 8w + (lane>>3) and j1 = j0 + 4; chunk gg.
    const int j0 = 8 * w + (lane >> 3);
    const int j1 = j0 + 4;
    const unsigned xrb = (unsigned)__cvta_generic_to_shared(&xr[0][0]);
    const unsigned xd0 = (unsigned)((j0 * 32 + 4 * (gg ^ (j0 & 7))) * 4);
    const unsigned xd1 = (unsigned)((j1 * 32 + 4 * (gg ^ (j1 & 7))) * 4);
    const int ebase = r * FLATS;           // + 32s + row

    // ---- prologue: stages 0..2 in flight
#pragma unroll
    for (int p = 0; p < DEPTH - 1; ++p) {
        const int e0 = g_e32[ebase + 32 * p + j0];
        const int e1 = g_e32[ebase + 32 * p + j1];
        const unsigned xs = (unsigned)(p * XSLOTF * 4);
        CP_ASYNC16(xrb + xs + xd0, g_xT + (size_t)e0 * 32 + 4 * gg);
        CP_ASYNC16(xrb + xs + xd1, g_xT + (size_t)e1 * 32 + 4 * gg);
        const unsigned ws = (unsigned)(p * WSLOTF * 4);
#pragma unroll
        for (int q = 0; q < 4; ++q)
            CP_ASYNC16(wrb + ws + wdst[q], wsrc[q] + 32 * p);
        CP_COMMIT();
    }

    // ---- main loop
    float acc[4][BATCH];
#pragma unroll
    for (int k = 0; k < 4; ++k)
#pragma unroll
        for (int b = 0; b < BATCH; ++b) acc[k][b] = 0.0f;

    const int swz = lane & 7;

#pragma unroll
    for (int s = 0; s < 16; ++s) {
        CP_WAIT2();            // own groups through stage s landed
        __syncthreads();       // all warps' x chunks visible; compute s-1 done

        const int slot = s & 3;

        // weights (own warp's private slot): 16 scalar LDS, 1 wf each
        const float* wp = &wr[w][slot][lane];
        float wv[4][4];
#pragma unroll
        for (int k = 0; k < 4; ++k)
#pragma unroll
            for (int i = 0; i < 4; ++i)
                wv[k][i] = wp[(k * 4 + i) * 32];

        // x: lane owns local row = lane (flat 32s+lane), all 8 batches
        const float4* __restrict__ rp =
            reinterpret_cast<const float4*>(&xr[slot][lane * 32]);
#pragma unroll
        for (int b = 0; b < BATCH; ++b) {
            float4 v = rp[b ^ swz];
#pragma unroll
            for (int k = 0; k < 4; ++k)
                acc[k][b] += v.x * wv[k][0] + v.y * wv[k][1]
                           + v.z * wv[k][2] + v.w * wv[k][3];
        }

        // prefetch stage nx into slot (s-1)&3 (safe: barrier above proves
        // every warp finished reading it in stage s-1)
        const int nx = s + DEPTH - 1;
        if (nx < 16) {
            const int e0 = g_e32[ebase + 32 * nx + j0];
            const int e1 = g_e32[ebase + 32 * nx + j1];
            const unsigned xs = (unsigned)((nx & 3) * XSLOTF * 4);
            CP_ASYNC16(xrb + xs + xd0, g_xT + (size_t)e0 * 32 + 4 * gg);
            CP_ASYNC16(xrb + xs + xd1, g_xT + (size_t)e1 * 32 + 4 * gg);
            const unsigned ws = (unsigned)((nx & 3) * WSLOTF * 4);
#pragma unroll
            for (int q = 0; q < 4; ++q)
                CP_ASYNC16(wrb + ws + wdst[q], wsrc[q] + 32 * nx);
        }
        CP_COMMIT();           // exactly one commit per stage (count invariant)
    }

    // ---- combine d-parities (lane <-> lane^16), write out
#pragma unroll
    for (int k = 0; k < 4; ++k)
#pragma unroll
        for (int b = 0; b < BATCH; ++b)
            acc[k][b] += __shfl_xor_sync(0xffffffffu, acc[k][b], 16);

    const int c    = lane & 15;
    const int half = lane >> 4;            // 0 -> batches 0..3, 1 -> 4..7
#pragma unroll
    for (int k = 0; k < 4; ++k) {
        const int n = r + NRES * (w + 4 * k);
#pragma unroll
        for (int m = 0; m < 4; ++m) {
            const int b = half * 4 + m;
            out[b * OUTPLANE + n * CH + c] = acc[k][b];
        }
    }
}

// ---------------------------------------------------------------------------
// Launch
// ---------------------------------------------------------------------------
extern "C" void kernel_launch(void* const* d_in, const int* in_sizes, int n_in,
                              void* d_out, int out_size) {
    const float* x     = (const float*)d_in[0];   // (8,10000,4) f32
    const void*  edges = d_in[1];                 // (320000,) int64/int32
    const float* W     = (const float*)d_in[2];   // (4,320000,16) f32
    float*       out   = (float*)d_out;           // (8,10000,16) f32
    (void)in_sizes; (void)n_in; (void)out_size;

    prep_kernel<<<640, 256>>>(x, edges);
    lcg_main<<<NRES, 128>>>(W, out);
}

// round 9
// speedup vs baseline: 1.2520x; 1.1220x over previous
#include <cuda_runtime.h>

// Problem constants (fixed by the reference)
#define NN        10000
#define DEG       32
#define CH        16
#define INDIM     4
#define BATCH     8
#define E_EDGES   (NN * DEG)       // 320000 = 512 * 625
#define WSTRIDE   (E_EDGES * CH)   // 5120000 floats between weight[i] planes
#define OUTPLANE  (NN * CH)
#define NRES      625              // residue classes: n mod 625
#define FLATS     512              // (d,c) pairs per node
#define DEPTH     4
#define XSLOTF    1024             // x slot: 32 rows * 32 floats (4 KB)
#define WSLOTF    256              // w slot per warp: 2n*4i*32 (1 KB)
#define NODE_OFF  (NRES * 8)       // node stride between a warp's two nodes

// Scratch (allocation-free: __device__ globals)
__device__ float g_xT[(NN + 1) * 32];   // [node][b*4+i], row NN = zeros
__device__ int   g_e32[E_EDGES];

#define CP_ASYNC16(dst_u32, src) \
    asm volatile("cp.async.cg.shared.global [%0], [%1], 16;" :: "r"(dst_u32), "l"(src))
#define CP_COMMIT() asm volatile("cp.async.commit_group;")
#define CP_WAIT2()  asm volatile("cp.async.wait_group 2;")

// ---------------------------------------------------------------------------
// Prep: per-block int64/int32 detection, narrow edges, transpose/pad x.
// ---------------------------------------------------------------------------
__global__ void prep_kernel(const float* __restrict__ x,
                            const void*  __restrict__ edges) {
    __shared__ int s_is32;
    const int t = threadIdx.x;
    if (t == 0) s_is32 = 0;
    __syncthreads();
    if (t < 64) {
        int slot = 2 * (t * 4999) + 1;   // odd int32 word: 0 iff int64 layout
        if (((const int*)edges)[slot] != 0) atomicOr(&s_is32, 1);
    }
    __syncthreads();
    const bool is32 = (s_is32 != 0);

    const int gtid = blockIdx.x * blockDim.x + t;
    const int nth  = gridDim.x * blockDim.x;

    if (is32) {
        const int* e = (const int*)edges;
        for (int j = gtid; j < E_EDGES; j += nth) g_e32[j] = e[j];
    } else {
        const long long* e = (const long long*)edges;
        for (int j = gtid; j < E_EDGES; j += nth) g_e32[j] = (int)e[j];
    }

    for (int j = gtid; j < (NN + 1) * 32; j += nth) {
        int node = j >> 5;
        int k    = j & 31;                 // k = b*4 + i
        float v  = 0.0f;
        if (node < NN) v = x[((k >> 2) * NN + node) * INDIM + (k & 3)];
        g_xT[j] = v;
    }
}

// ---------------------------------------------------------------------------
// Main: block (256 thr, 8 warps) = one residue class r.
// Warp w computes nA = r + 625*w, nB = r + 625*(w+8).
// Stage s covers flats 32s..32s+31 (d = 2s+dpar, lane = 16*dpar + c).
//  - x: block-shared 4-deep cp.async ring of 32 gathered rows (XOR-swizzled);
//       fill task: thread t -> row t>>3, chunk t&7 (coalesced per 8 lanes).
//  - w: per-warp 4-deep private ring, 2 nodes * 4 planes * 32 floats / slot.
// One __syncthreads per stage. 48 KB smem, <=64 regs -> 4 blocks (32 warps)/SM.
// ---------------------------------------------------------------------------
__global__ __launch_bounds__(256, 4)
void lcg_main(const float* __restrict__ W, float* __restrict__ out) {
    __shared__ __align__(16) float xr[DEPTH][XSLOTF];      // 16384 B
    __shared__ __align__(16) float wr[8][DEPTH][WSLOTF];   // 32768 B
    const int r    = blockIdx.x;
    const int tid  = threadIdx.x;
    const int w    = tid >> 5;
    const int lane = tid & 31;

    // ---- x-ring fill geometry: row j = tid>>3, chunk gg = tid&7
    const int jx = tid >> 3;
    const int gx = tid & 7;
    const unsigned xrb = (unsigned)__cvta_generic_to_shared(&xr[0][0]);
    const unsigned xd  = (unsigned)((jx * 32 + 4 * (gx ^ (jx & 7))) * 4);
    const int ebase = r * FLATS;

    // ---- w-ring fill geometry: per thread 2 tasks (node 0/1 of this warp)
    const int ii = lane >> 3, gg = lane & 7;
    const float* wsrcA = W + (size_t)ii * WSTRIDE
                           + (size_t)(r + NRES * w) * FLATS + 4 * gg;
    const float* wsrcB = wsrcA + (size_t)NODE_OFF * FLATS;
    const unsigned wrb = (unsigned)__cvta_generic_to_shared(&wr[w][0][0]);
    const unsigned wdA = (unsigned)((ii * 32 + 4 * gg) * 4);
    const unsigned wdB = wdA + 128 * 4;

    // ---- prologue: stages 0..2 in flight
#pragma unroll
    for (int p = 0; p < DEPTH - 1; ++p) {
        const int e0 = g_e32[ebase + 32 * p + jx];
        CP_ASYNC16(xrb + (unsigned)(p * XSLOTF * 4) + xd,
                   g_xT + (size_t)e0 * 32 + 4 * gx);
        const unsigned ws = (unsigned)(p * WSLOTF * 4);
        CP_ASYNC16(wrb + ws + wdA, wsrcA + 32 * p);
        CP_ASYNC16(wrb + ws + wdB, wsrcB + 32 * p);
        CP_COMMIT();
    }

    // ---- main loop
    float accA[BATCH], accB[BATCH];
#pragma unroll
    for (int b = 0; b < BATCH; ++b) { accA[b] = 0.0f; accB[b] = 0.0f; }

    const int swz = lane & 7;

#pragma unroll
    for (int s = 0; s < 16; ++s) {
        CP_WAIT2();            // own groups through stage s landed
        __syncthreads();       // all threads' x chunks visible; s-1 reads done

        const int slot = s & 3;

        const float* wp = &wr[w][slot][lane];
        const float a0 = wp[0],   a1 = wp[32],  a2 = wp[64],  a3 = wp[96];
        const float b0 = wp[128], b1 = wp[160], b2 = wp[192], b3 = wp[224];

        const float4* __restrict__ rp =
            reinterpret_cast<const float4*>(&xr[slot][lane * 32]);
#pragma unroll
        for (int b = 0; b < BATCH; ++b) {
            float4 v = rp[b ^ swz];        // logical batch b (swizzled)
            accA[b] += v.x * a0 + v.y * a1 + v.z * a2 + v.w * a3;
            accB[b] += v.x * b0 + v.y * b1 + v.z * b2 + v.w * b3;
        }

        // refill slot (s-1)&3: barrier above proves all reads of it finished
        const int nx = s + DEPTH - 1;
        if (nx < 16) {
            const int e0 = g_e32[ebase + 32 * nx + jx];
            CP_ASYNC16(xrb + (unsigned)((nx & 3) * XSLOTF * 4) + xd,
                       g_xT + (size_t)e0 * 32 + 4 * gx);
            const unsigned ws = (unsigned)((nx & 3) * WSLOTF * 4);
            CP_ASYNC16(wrb + ws + wdA, wsrcA + 32 * nx);
            CP_ASYNC16(wrb + ws + wdB, wsrcB + 32 * nx);
        }
        CP_COMMIT();           // exactly one commit per stage
    }

    // ---- combine d-parities (lane <-> lane^16), write out
#pragma unroll
    for (int b = 0; b < BATCH; ++b) {
        accA[b] += __shfl_xor_sync(0xffffffffu, accA[b], 16);
        accB[b] += __shfl_xor_sync(0xffffffffu, accB[b], 16);
    }

    const int nA = r + NRES * w;
    const int nB = nA + NODE_OFF;
    const int c    = lane & 15;
    const int half = lane >> 4;            // 0 -> batches 0..3, 1 -> 4..7
#pragma unroll
    for (int k = 0; k < 4; ++k) {
        const int b = half * 4 + k;
        out[b * OUTPLANE + nA * CH + c] = half ? accA[k + 4] : accA[k];
        out[b * OUTPLANE + nB * CH + c] = half ? accB[k + 4] : accB[k];
    }
}

// ---------------------------------------------------------------------------
// Launch
// ---------------------------------------------------------------------------
extern "C" void kernel_launch(void* const* d_in, const int* in_sizes, int n_in,
                              void* d_out, int out_size) {
    const float* x     = (const float*)d_in[0];   // (8,10000,4) f32
    const void*  edges = d_in[1];                 // (320000,) int64/int32
    const float* W     = (const float*)d_in[2];   // (4,320000,16) f32
    float*       out   = (float*)d_out;           // (8,10000,16) f32
    (void)in_sizes; (void)n_in; (void)out_size;

    prep_kernel<<<640, 256>>>(x, edges);
    lcg_main<<<NRES, 256>>>(W, out);
}

// round 10
// speedup vs baseline: 1.3568x; 1.0837x over previous
#include <cuda_runtime.h>

// Problem constants (fixed by the reference)
#define NN        10000
#define DEG       32
#define CH        16
#define INDIM     4
#define BATCH     8
#define E_EDGES   (NN * DEG)       // 320000 = 512 * 625
#define WSTRIDE   (E_EDGES * CH)   // 5120000 floats between weight[i] planes
#define OUTPLANE  (NN * CH)
#define NRES      625              // residue classes: n mod 625
#define FLATS     512              // (d,c) pairs per node
#define DEPTH     4
#define XSLOTF    1024             // x slot: 32 rows * 32 floats (4 KB)
#define WSLOTF    256              // w slot per warp: 2n*4i*32 (1 KB)
#define NODE_OFF  (NRES * 8)       // node stride between a warp's two nodes

// Scratch (allocation-free: __device__ globals)
__device__ float g_xT[(NN + 1) * 32];   // [node][b*4+i], row NN = zeros
__device__ int   g_e32[E_EDGES];

#define CP_ASYNC16(dst_u32, src) \
    asm volatile("cp.async.cg.shared.global [%0], [%1], 16;" :: "r"(dst_u32), "l"(src))
#define CP_COMMIT() asm volatile("cp.async.commit_group;")
#define CP_WAIT2()  asm volatile("cp.async.wait_group 2;")

// ---------------------------------------------------------------------------
// Prep: per-block int64/int32 detection, narrow edges, transpose/pad x.
// ---------------------------------------------------------------------------
__global__ void prep_kernel(const float* __restrict__ x,
                            const void*  __restrict__ edges) {
    __shared__ int s_is32;
    const int t = threadIdx.x;
    if (t == 0) s_is32 = 0;
    __syncthreads();
    if (t < 64) {
        int slot = 2 * (t * 4999) + 1;   // odd int32 word: 0 iff int64 layout
        if (((const int*)edges)[slot] != 0) atomicOr(&s_is32, 1);
    }
    __syncthreads();
    const bool is32 = (s_is32 != 0);

    const int gtid = blockIdx.x * blockDim.x + t;
    const int nth  = gridDim.x * blockDim.x;

    if (is32) {
        const int* e = (const int*)edges;
        for (int j = gtid; j < E_EDGES; j += nth) g_e32[j] = e[j];
    } else {
        const long long* e = (const long long*)edges;
        for (int j = gtid; j < E_EDGES; j += nth) g_e32[j] = (int)e[j];
    }

    for (int j = gtid; j < (NN + 1) * 32; j += nth) {
        int node = j >> 5;
        int k    = j & 31;                 // k = b*4 + i
        float v  = 0.0f;
        if (node < NN) v = x[((k >> 2) * NN + node) * INDIM + (k & 3)];
        g_xT[j] = v;
    }
}

// ---------------------------------------------------------------------------
// Main: block (256 thr, 8 warps) = one residue class r.
// Warp w computes nA = r + 625*w, nB = r + 625*(w+8).
// Stage s covers flats 32s..32s+31 (d = 2s+dpar, lane = 16*dpar + c).
//  - edges: the block's 512 indices preloaded into smem ONCE (kills the
//    per-stage convoyed LDG on the refill critical path).
//  - x: block-shared 4-deep cp.async ring of 32 gathered rows (XOR-swizzled).
//  - w: per-warp 4-deep private ring, 2 nodes * 4 planes * 32 floats / slot.
// One __syncthreads per stage. 50 KB smem, <=64 regs -> 4 blocks/SM.
// ---------------------------------------------------------------------------
__global__ __launch_bounds__(256, 4)
void lcg_main(const float* __restrict__ W, float* __restrict__ out) {
    __shared__ __align__(16) float xr[DEPTH][XSLOTF];      // 16384 B
    __shared__ __align__(16) float wr[8][DEPTH][WSLOTF];   // 32768 B
    __shared__ int se[FLATS];                               // 2048 B
    const int r    = blockIdx.x;
    const int tid  = threadIdx.x;
    const int w    = tid >> 5;
    const int lane = tid & 31;

    // ---- preload this residue class's edge list (coalesced, once)
    se[tid]       = g_e32[r * FLATS + tid];
    se[tid + 256] = g_e32[r * FLATS + tid + 256];
    __syncthreads();

    // ---- x-ring fill geometry: row jx = tid>>3, chunk gx = tid&7
    const int jx = tid >> 3;
    const int gx = tid & 7;
    const unsigned xrb = (unsigned)__cvta_generic_to_shared(&xr[0][0]);
    const unsigned xd  = (unsigned)((jx * 32 + 4 * (gx ^ (jx & 7))) * 4);

    // ---- w-ring fill geometry: per thread 2 tasks (this warp's two nodes)
    const int ii = lane >> 3, gg = lane & 7;
    const float* wsrcA = W + (size_t)ii * WSTRIDE
                           + (size_t)(r + NRES * w) * FLATS + 4 * gg;
    const float* wsrcB = wsrcA + (size_t)NODE_OFF * FLATS;
    const unsigned wrb = (unsigned)__cvta_generic_to_shared(&wr[w][0][0]);
    const unsigned wdA = (unsigned)((ii * 32 + 4 * gg) * 4);
    const unsigned wdB = wdA + 128 * 4;

    // ---- prologue: stages 0..2 in flight
#pragma unroll
    for (int p = 0; p < DEPTH - 1; ++p) {
        const int e0 = se[32 * p + jx];
        CP_ASYNC16(xrb + (unsigned)(p * XSLOTF * 4) + xd,
                   g_xT + (size_t)e0 * 32 + 4 * gx);
        const unsigned ws = (unsigned)(p * WSLOTF * 4);
        CP_ASYNC16(wrb + ws + wdA, wsrcA + 32 * p);
        CP_ASYNC16(wrb + ws + wdB, wsrcB + 32 * p);
        CP_COMMIT();
    }

    // ---- main loop
    float accA[BATCH], accB[BATCH];
#pragma unroll
    for (int b = 0; b < BATCH; ++b) { accA[b] = 0.0f; accB[b] = 0.0f; }

    const int swz = lane & 7;

#pragma unroll
    for (int s = 0; s < 16; ++s) {
        CP_WAIT2();            // own groups through stage s landed
        __syncthreads();       // all x chunks visible; stage s-1 reads done

        const int slot = s & 3;
        const int nx = s + DEPTH - 1;

        // issue next stage's edge index read early (LDS, hidden by compute)
        int e0 = 0;
        if (nx < 16) e0 = se[32 * nx + jx];

        const float* wp = &wr[w][slot][lane];
        const float a0 = wp[0],   a1 = wp[32],  a2 = wp[64],  a3 = wp[96];
        const float b0 = wp[128], b1 = wp[160], b2 = wp[192], b3 = wp[224];

        const float4* __restrict__ rp =
            reinterpret_cast<const float4*>(&xr[slot][lane * 32]);
#pragma unroll
        for (int b = 0; b < BATCH; ++b) {
            float4 v = rp[b ^ swz];        // logical batch b (swizzled)
            accA[b] += v.x * a0 + v.y * a1 + v.z * a2 + v.w * a3;
            accB[b] += v.x * b0 + v.y * b1 + v.z * b2 + v.w * b3;
        }

        // refill slot (s-1)&3: barrier above proves all reads of it finished
        if (nx < 16) {
            CP_ASYNC16(xrb + (unsigned)((nx & 3) * XSLOTF * 4) + xd,
                       g_xT + (size_t)e0 * 32 + 4 * gx);
            const unsigned ws = (unsigned)((nx & 3) * WSLOTF * 4);
            CP_ASYNC16(wrb + ws + wdA, wsrcA + 32 * nx);
            CP_ASYNC16(wrb + ws + wdB, wsrcB + 32 * nx);
        }
        CP_COMMIT();           // exactly one commit per stage
    }

    // ---- combine d-parities (lane <-> lane^16), write out
#pragma unroll
    for (int b = 0; b < BATCH; ++b) {
        accA[b] += __shfl_xor_sync(0xffffffffu, accA[b], 16);
        accB[b] += __shfl_xor_sync(0xffffffffu, accB[b], 16);
    }

    const int nA = r + NRES * w;
    const int nB = nA + NODE_OFF;
    const int c    = lane & 15;
    const int half = lane >> 4;            // 0 -> batches 0..3, 1 -> 4..7
#pragma unroll
    for (int k = 0; k < 4; ++k) {
        const int b = half * 4 + k;
        out[b * OUTPLANE + nA * CH + c] = half ? accA[k + 4] : accA[k];
        out[b * OUTPLANE + nB * CH + c] = half ? accB[k + 4] : accB[k];
    }
}

// ---------------------------------------------------------------------------
// Launch
// ---------------------------------------------------------------------------
extern "C" void kernel_launch(void* const* d_in, const int* in_sizes, int n_in,
                              void* d_out, int out_size) {
    const float* x     = (const float*)d_in[0];   // (8,10000,4) f32
    const void*  edges = d_in[1];                 // (320000,) int64/int32
    const float* W     = (const float*)d_in[2];   // (4,320000,16) f32
    float*       out   = (float*)d_out;           // (8,10000,16) f32
    (void)in_sizes; (void)n_in; (void)out_size;

    prep_kernel<<<640, 256>>>(x, edges);
    lcg_main<<<NRES, 256>>>(W, out);
}